// round 3
// baseline (speedup 1.0000x reference)
#include <cuda_runtime.h>
#include <cuda_bf16.h>

#define Bn 8
#define Sn 512
#define Kn 16
#define Rr 16           // output rows per block in main kernel
#define EMPTY_DIST 362.1f

// Persistent scratch (no allocations allowed). Starts zeroed (.bss);
// the last main block resets everything after use -> deterministic replays.
__device__ float    g_py[Bn][Kn];
__device__ float    g_px[Bn][Kn];
__device__ int      g_cnt[Bn];
__device__ unsigned g_maxbits[Bn];   // per-batch max of thresholded distance (float bits, >=0)
__device__ double   g_numer[Bn];     // per-batch sum(pred * _distance_unnormalized)
__device__ double   g_gradsum;       // global sum of gradient map
__device__ unsigned g_done;          // finished-block counter for main kernel

// ---------------------------------------------------------------------------
// Kernel 1: collect nonzero label pixels. Wide grid: (slices, Bn).
// Relies on g_cnt == 0 at entry (zeroed by .bss init / previous finalize).
// ---------------------------------------------------------------------------
#define CSLICES 64
__global__ __launch_bounds__(256) void collect_kernel(const float* __restrict__ pt) {
    const int b = blockIdx.y;
    const int slice = blockIdx.x;
    const int n4_per_slice = (Sn * Sn / 4) / CSLICES;      // 1024 float4
    const float4* p = (const float4*)(pt + (size_t)b * Sn * Sn) + slice * n4_per_slice;
    for (int i = threadIdx.x; i < n4_per_slice; i += 256) {
        float4 v = p[i];
        if (v.x != 0.f || v.y != 0.f || v.z != 0.f || v.w != 0.f) {
            float vv[4] = {v.x, v.y, v.z, v.w};
            int base_idx = (slice * n4_per_slice + i) * 4;
            #pragma unroll
            for (int j = 0; j < 4; j++) {
                if (vv[j] != 0.f) {
                    int idx = base_idx + j;
                    int slot = atomicAdd(&g_cnt[b], 1);
                    if (slot < Kn) {
                        g_py[b][slot] = (float)(idx / Sn);
                        g_px[b][slot] = (float)(idx % Sn);
                    }
                }
            }
        }
    }
}

// ---------------------------------------------------------------------------
// Kernel 2: fused distance + sobel + reductions + finalize (last block).
// grid (Sn/Rr, Bn), block Sn threads.
// ---------------------------------------------------------------------------
__global__ __launch_bounds__(Sn) void main_kernel(const float* __restrict__ pred,
                                                  const float* __restrict__ ori,
                                                  float* __restrict__ out) {
    __shared__ float s_img[Rr + 2][Sn];
    __shared__ float s_py[Kn], s_px[Kn];
    __shared__ int   s_cnt;
    __shared__ float sh_s[16], sh_g[16], sh_m[16];

    const int y0 = blockIdx.x * Rr;
    const int b  = blockIdx.y;
    const int x  = threadIdx.x;
    const size_t base = (size_t)b * Sn * Sn;

    if (x < Kn) { s_py[x] = g_py[b][x]; s_px[x] = g_px[b][x]; }
    if (x == 0) { int c = g_cnt[b]; s_cnt = (c > Kn) ? Kn : c; }

    float pv[Rr];
    // load rows y0-1 .. y0+Rr into shared (img = pred*ori), keep middle pred in regs
    #pragma unroll
    for (int rr = 0; rr < Rr + 2; rr++) {
        int yy = y0 - 1 + rr;
        float pval = 0.f, v = 0.f;
        if (yy >= 0 && yy < Sn) {
            size_t o = base + (size_t)yy * Sn + x;
            pval = pred[o];
            v = pval * ori[o];
        }
        s_img[rr][x] = v;
        if (rr >= 1 && rr <= Rr) pv[rr - 1] = pval;
    }
    __syncthreads();

    const int cnt = s_cnt;
    const float fx = (float)x;

    float vsum = 0.f, gsum = 0.f, vmax = 0.f;

    #pragma unroll
    for (int r = 0; r < Rr; r++) {
        const int y = y0 + r;
        // --- distance (squared distances exact in fp32; sqrt once) ---
        float d2min = 3.4e38f;
        const float fy = (float)y;
        for (int i = 0; i < cnt; i++) {
            float dy = fy - s_py[i];
            float dx = fx - s_px[i];
            d2min = fminf(d2min, fmaf(dy, dy, dx * dx));
        }
        float dist = (cnt > 0) ? sqrtf(d2min) : EMPTY_DIST;
        float dd = (dist > 1.0f) ? (dist - 1.0f) : 0.f;
        vsum += pv[r] * dd;
        vmax = fmaxf(vmax, dd);

        // --- gradient (interior only) ---
        if (y >= 1 && y <= Sn - 2 && x >= 1 && x <= Sn - 2) {
            float n00 = s_img[r][x - 1],     n01 = s_img[r][x],     n02 = s_img[r][x + 1];
            float n10 = s_img[r + 1][x - 1],                        n12 = s_img[r + 1][x + 1];
            float n20 = s_img[r + 2][x - 1], n21 = s_img[r + 2][x], n22 = s_img[r + 2][x + 1];
            float g0 = (n02 - n00) + 2.f * (n12 - n10) + (n22 - n20);
            float g1 = (n00 - n20) + 2.f * (n01 - n21) + (n02 - n22);
            float g2 = 2.f * (n00 - n22) + (n01 - n21) + (n10 - n12);
            float g3 = (n01 - n21) + 2.f * (n02 - n20) + (n12 - n10);
            gsum += fmaxf(fmaxf(fabsf(g0), fabsf(g1)), fmaxf(fabsf(g2), fabsf(g3)));
        }
    }

    // --- block reduction: sum(vsum), sum(gsum), max(vmax) ---
    #pragma unroll
    for (int o = 16; o > 0; o >>= 1) {
        vsum += __shfl_down_sync(0xffffffffu, vsum, o);
        gsum += __shfl_down_sync(0xffffffffu, gsum, o);
        vmax = fmaxf(vmax, __shfl_down_sync(0xffffffffu, vmax, o));
    }
    const int wid = x >> 5, lane = x & 31;
    if (lane == 0) { sh_s[wid] = vsum; sh_g[wid] = gsum; sh_m[wid] = vmax; }
    __syncthreads();
    if (wid == 0) {
        vsum = (lane < 16) ? sh_s[lane] : 0.f;
        gsum = (lane < 16) ? sh_g[lane] : 0.f;
        vmax = (lane < 16) ? sh_m[lane] : 0.f;
        #pragma unroll
        for (int o = 8; o > 0; o >>= 1) {
            vsum += __shfl_down_sync(0xffffffffu, vsum, o);
            gsum += __shfl_down_sync(0xffffffffu, gsum, o);
            vmax = fmaxf(vmax, __shfl_down_sync(0xffffffffu, vmax, o));
        }
        if (lane == 0) {
            atomicAdd(&g_numer[b], (double)vsum);
            atomicAdd(&g_gradsum, (double)gsum);
            atomicMax(&g_maxbits[b], __float_as_uint(vmax));

            // --- last-block finalize + reset for next replay ---
            __threadfence();
            unsigned ticket = atomicAdd(&g_done, 1u);
            const unsigned total = (Sn / Rr) * Bn;
            if (ticket == total - 1u) {
                double acc = 0.0;
                #pragma unroll
                for (int bb = 0; bb < Bn; bb++) {
                    float mx = __uint_as_float(g_maxbits[bb]);
                    acc += g_numer[bb] / (double)mx;
                    // reset per-batch state
                    g_numer[bb] = 0.0;
                    g_maxbits[bb] = 0u;
                    g_cnt[bb] = 0;
                }
                const double denom = (double)Sn * (double)Sn * (double)Bn;
                out[0] = (float)(acc / denom);
                out[1] = (float)(g_gradsum / denom);
                g_gradsum = 0.0;
                g_done = 0u;
                __threadfence();
            }
        }
    }
}

extern "C" void kernel_launch(void* const* d_in, const int* in_sizes, int n_in,
                              void* d_out, int out_size) {
    const float* pred = (const float*)d_in[0];
    const float* ptl  = (const float*)d_in[1];
    const float* ori  = (const float*)d_in[2];
    float* out = (float*)d_out;

    collect_kernel<<<dim3(CSLICES, Bn), 256>>>(ptl);
    main_kernel<<<dim3(Sn / Rr, Bn), Sn>>>(pred, ori, out);
}

// round 4
// speedup vs baseline: 1.2927x; 1.2927x over previous
#include <cuda_runtime.h>
#include <cuda_bf16.h>

#define Bn 8
#define Sn 512
#define Kn 16
#define Rr 8            // output rows per block in main kernel
#define EMPTY_DIST 362.1f
#define FAR_COORD 1.0e18f

// Persistent scratch (no allocations allowed). Starts zeroed (.bss);
// the last main block resets counters after use -> deterministic replays.
__device__ float    g_py[Bn][Kn];
__device__ float    g_px[Bn][Kn];
__device__ int      g_cnt[Bn];
__device__ unsigned g_maxbits[Bn];   // per-batch max of thresholded distance (float bits, >=0)
__device__ double   g_numer[Bn];     // per-batch sum(pred * _distance_unnormalized)
__device__ double   g_gradsum;       // global sum of gradient map
__device__ unsigned g_done;          // finished-block counter for main kernel

// ---------------------------------------------------------------------------
// Kernel 1: collect nonzero label pixels. Wide grid: (slices, Bn).
// ---------------------------------------------------------------------------
#define CSLICES 64
__global__ __launch_bounds__(256) void collect_kernel(const float* __restrict__ pt) {
    const int b = blockIdx.y;
    const int slice = blockIdx.x;
    const int n4_per_slice = (Sn * Sn / 4) / CSLICES;      // 1024 float4
    const float4* p = (const float4*)(pt + (size_t)b * Sn * Sn) + slice * n4_per_slice;
    for (int i = threadIdx.x; i < n4_per_slice; i += 256) {
        float4 v = p[i];
        if (v.x != 0.f || v.y != 0.f || v.z != 0.f || v.w != 0.f) {
            float vv[4] = {v.x, v.y, v.z, v.w};
            int base_idx = (slice * n4_per_slice + i) * 4;
            #pragma unroll
            for (int j = 0; j < 4; j++) {
                if (vv[j] != 0.f) {
                    int idx = base_idx + j;
                    int slot = atomicAdd(&g_cnt[b], 1);
                    if (slot < Kn) {
                        g_py[b][slot] = (float)(idx / Sn);
                        g_px[b][slot] = (float)(idx % Sn);
                    }
                }
            }
        }
    }
}

// ---------------------------------------------------------------------------
// Kernel 2: fused distance + sobel + reductions + finalize (last block).
// grid (Sn/Rr, Bn), block Sn threads, 3 blocks/SM.
// ---------------------------------------------------------------------------
__global__ __launch_bounds__(Sn, 3) void main_kernel(const float* __restrict__ pred,
                                                     const float* __restrict__ ori,
                                                     float* __restrict__ out) {
    __shared__ float s_img[Rr + 2][Sn];
    __shared__ float s_py[Kn], s_px[Kn];
    __shared__ int   s_cnt;
    __shared__ float sh_s[16], sh_g[16], sh_m[16];

    const int y0 = blockIdx.x * Rr;
    const int b  = blockIdx.y;
    const int x  = threadIdx.x;
    const size_t base = (size_t)b * Sn * Sn;

    if (x < Kn) {
        int c = g_cnt[b]; c = (c > Kn) ? Kn : c;
        // pad invalid slots with far coordinates so the point loop unrolls cleanly
        s_py[x] = (x < c) ? g_py[b][x] : FAR_COORD;
        s_px[x] = (x < c) ? g_px[b][x] : FAR_COORD;
        if (x == 0) s_cnt = c;
    }

    float pv[Rr];
    // load rows y0-1 .. y0+Rr into shared (img = pred*ori), keep middle pred in regs
    #pragma unroll
    for (int rr = 0; rr < Rr + 2; rr++) {
        int yy = y0 - 1 + rr;
        float pval = 0.f, v = 0.f;
        if (yy >= 0 && yy < Sn) {
            size_t o = base + (size_t)yy * Sn + x;
            pval = pred[o];
            v = pval * ori[o];
        }
        s_img[rr][x] = v;
        if (rr >= 1 && rr <= Rr) pv[rr - 1] = pval;
    }
    __syncthreads();

    const float fx  = (float)x;
    const float fy0 = (float)y0;

    // --- distance: point-outer, row-inner. dx^2 computed once per point. ---
    float d2min[Rr];
    #pragma unroll
    for (int r = 0; r < Rr; r++) d2min[r] = 3.4e38f;

    #pragma unroll
    for (int i = 0; i < Kn; i++) {
        float dxv = fx - s_px[i];
        float dx2 = dxv * dxv;
        float dy0 = fy0 - s_py[i];
        #pragma unroll
        for (int r = 0; r < Rr; r++) {
            float dy = dy0 + (float)r;
            d2min[r] = fminf(d2min[r], fmaf(dy, dy, dx2));
        }
    }

    const int cnt = s_cnt;
    float vsum = 0.f, gsum = 0.f, vmax = 0.f;

    #pragma unroll
    for (int r = 0; r < Rr; r++) {
        const int y = y0 + r;
        float dist = (cnt > 0) ? sqrtf(d2min[r]) : EMPTY_DIST;
        float dd = (dist > 1.0f) ? (dist - 1.0f) : 0.f;
        vsum += pv[r] * dd;
        vmax = fmaxf(vmax, dd);

        // --- gradient (interior only) ---
        if (y >= 1 && y <= Sn - 2 && x >= 1 && x <= Sn - 2) {
            float n00 = s_img[r][x - 1],     n01 = s_img[r][x],     n02 = s_img[r][x + 1];
            float n10 = s_img[r + 1][x - 1],                        n12 = s_img[r + 1][x + 1];
            float n20 = s_img[r + 2][x - 1], n21 = s_img[r + 2][x], n22 = s_img[r + 2][x + 1];
            float g0 = (n02 - n00) + 2.f * (n12 - n10) + (n22 - n20);
            float g1 = (n00 - n20) + 2.f * (n01 - n21) + (n02 - n22);
            float g2 = 2.f * (n00 - n22) + (n01 - n21) + (n10 - n12);
            float g3 = (n01 - n21) + 2.f * (n02 - n20) + (n12 - n10);
            gsum += fmaxf(fmaxf(fabsf(g0), fabsf(g1)), fmaxf(fabsf(g2), fabsf(g3)));
        }
    }

    // --- block reduction: sum(vsum), sum(gsum), max(vmax) ---
    #pragma unroll
    for (int o = 16; o > 0; o >>= 1) {
        vsum += __shfl_down_sync(0xffffffffu, vsum, o);
        gsum += __shfl_down_sync(0xffffffffu, gsum, o);
        vmax = fmaxf(vmax, __shfl_down_sync(0xffffffffu, vmax, o));
    }
    const int wid = x >> 5, lane = x & 31;
    if (lane == 0) { sh_s[wid] = vsum; sh_g[wid] = gsum; sh_m[wid] = vmax; }
    __syncthreads();
    if (wid == 0) {
        vsum = (lane < 16) ? sh_s[lane] : 0.f;
        gsum = (lane < 16) ? sh_g[lane] : 0.f;
        vmax = (lane < 16) ? sh_m[lane] : 0.f;
        #pragma unroll
        for (int o = 8; o > 0; o >>= 1) {
            vsum += __shfl_down_sync(0xffffffffu, vsum, o);
            gsum += __shfl_down_sync(0xffffffffu, gsum, o);
            vmax = fmaxf(vmax, __shfl_down_sync(0xffffffffu, vmax, o));
        }
        if (lane == 0) {
            atomicAdd(&g_numer[b], (double)vsum);
            atomicAdd(&g_gradsum, (double)gsum);
            atomicMax(&g_maxbits[b], __float_as_uint(vmax));

            // --- last-block finalize + reset for next replay ---
            __threadfence();
            unsigned ticket = atomicAdd(&g_done, 1u);
            const unsigned total = (Sn / Rr) * Bn;
            if (ticket == total - 1u) {
                double acc = 0.0;
                #pragma unroll
                for (int bb = 0; bb < Bn; bb++) {
                    float mx = __uint_as_float(g_maxbits[bb]);
                    acc += g_numer[bb] / (double)mx;
                    g_numer[bb] = 0.0;
                    g_maxbits[bb] = 0u;
                    g_cnt[bb] = 0;
                }
                const double denom = (double)Sn * (double)Sn * (double)Bn;
                out[0] = (float)(acc / denom);
                out[1] = (float)(g_gradsum / denom);
                g_gradsum = 0.0;
                g_done = 0u;
                __threadfence();
            }
        }
    }
}

extern "C" void kernel_launch(void* const* d_in, const int* in_sizes, int n_in,
                              void* d_out, int out_size) {
    const float* pred = (const float*)d_in[0];
    const float* ptl  = (const float*)d_in[1];
    const float* ori  = (const float*)d_in[2];
    float* out = (float*)d_out;

    collect_kernel<<<dim3(CSLICES, Bn), 256>>>(ptl);
    main_kernel<<<dim3(Sn / Rr, Bn), Sn>>>(pred, ori, out);
}